// round 8
// baseline (speedup 1.0000x reference)
#include <cuda_runtime.h>

// EHD layer v7: barrier-free marching-column kernel.
//   3x3 conv (8 filters) -> argmax+thresh -> byte-packed one-hot (u64) ->
//   separable 5x5 box sum -> magic-number unpack -> out[B,9,1018,1018].
//
// Structure: grid = 37 col-strips x 16 batch = 592 CTAs (one wave at
// 4 CTAs/SM). CTA = 8 warps; warp w marches output rows [w*128, w*128+128)
// of a 28-wide strip. Per 4-row block, all state in registers:
//   - input window: rolling 6 rows x 3 cols (predicated LDG, L1 hits)
//   - horizontal 5-tap: shfl_down on the packed u64 (lane = column)
//   - vertical 5-tap: 8-slot register ring
// Zero __syncthreads after the one-time mask load. Masks in smem (LDS
// floor 2/issue) instead of constant bank (LDC floor 8/issue).

#define NOR    8
#define OUT_H  1018
#define OUT_W  1018
#define THRESH 0.9f
#define SW     28            // strip width (output cols per CTA)
#define ROWS_W 128           // output rows per warp

typedef unsigned long long u64;

__device__ __forceinline__ float cnt_scale(unsigned word, int byte_sel) {
    // word's byte[byte_sel] = count in 0..25 -> count * fl(1/25), exact
    const unsigned bits = __byte_perm(word, 0x4B000000u, 0x7440 | byte_sel);
    return fmaf(__int_as_float(bits), (1.0f / 25.0f),
                -(8388608.0f * (1.0f / 25.0f)));
}

__global__ __launch_bounds__(256, 4)
void ehd_march_kernel(const float* __restrict__ x,
                      const float* __restrict__ masks,
                      float* __restrict__ out)
{
    __shared__ float s_m[NOR * 12];   // filter f at f*12 (16B-aligned), taps 0..8

    const int tid  = threadIdx.x;
    const int lane = tid & 31;
    const int wrp  = tid >> 5;

    if (tid < NOR * 9) {
        const int f = tid / 9, j = tid - f * 9;
        s_m[f * 12 + j] = masks[tid];
    }
    __syncthreads();   // the only barrier

    const int ox  = blockIdx.x * SW;
    const int b   = blockIdx.y;
    const float* xb = x + (size_t)b * (1024 * 1024);

    const int gx0 = ox + lane;             // this lane's index column
    const bool px0 = (gx0     < 1024);
    const bool px1 = (gx0 + 1 < 1024);
    const bool px2 = (gx0 + 2 < 1024);
    const bool colv = (lane < SW) && (gx0 < OUT_W);   // valid output column

    const int i0 = wrp * ROWS_W;           // first index row for this warp

    // rolling input window: rows w[0..5], 3 cols each
    float w[6][3];
    // h ring: slots 0..7 = index rows (ib-4)..(ib+3) after each block
    u64 h[8];
#pragma unroll
    for (int j = 0; j < 8; j++) h[j] = 0ULL;

    // prologue: input rows i0, i0+1 -> w[0], w[1] (always < 1024)
#pragma unroll
    for (int j = 0; j < 2; j++) {
        const float* row = xb + (i0 + j) * 1024 + gx0;
        w[j][0] = px0 ? row[0] : 0.0f;
        w[j][1] = px1 ? row[1] : 0.0f;
        w[j][2] = px2 ? row[2] : 0.0f;
    }

    const size_t plane = (size_t)OUT_H * OUT_W;
    float* ob = out + (size_t)b * 9 * plane;

#pragma unroll 1
    for (int k = 0; k <= ROWS_W / 4; k++) {
        const int ib = i0 + (k << 2);      // block's first index row

        // ---- load 4 new input rows (ib+2 .. ib+5) ----
#pragma unroll
        for (int p = 0; p < 4; p++) {
            const int gy = ib + 2 + p;
            if (gy < 1024) {
                const float* row = xb + gy * 1024 + gx0;
                w[2 + p][0] = px0 ? row[0] : 0.0f;
                w[2 + p][1] = px1 ? row[1] : 0.0f;
                w[2 + p][2] = px2 ? row[2] : 0.0f;
            } else {
                w[2 + p][0] = 0.0f; w[2 + p][1] = 0.0f; w[2 + p][2] = 0.0f;
            }
        }

        // ---- conv (8 filters) + argmax + threshold for 4 index rows ----
        float best[4];
        int   bi[4];
#pragma unroll
        for (int p = 0; p < 4; p++) { best[p] = -3.4e38f; bi[p] = 0; }

#pragma unroll
        for (int f = 0; f < NOR; f++) {
            const float4 m0 = *(const float4*)&s_m[f * 12];
            const float4 m1 = *(const float4*)&s_m[f * 12 + 4];
            const float  m8 = s_m[f * 12 + 8];
#pragma unroll
            for (int p = 0; p < 4; p++) {
                float acc = w[p][0] * m0.x;
                acc = fmaf(w[p    ][1], m0.y, acc);
                acc = fmaf(w[p    ][2], m0.z, acc);
                acc = fmaf(w[p + 1][0], m0.w, acc);
                acc = fmaf(w[p + 1][1], m1.x, acc);
                acc = fmaf(w[p + 1][2], m1.y, acc);
                acc = fmaf(w[p + 2][0], m1.z, acc);
                acc = fmaf(w[p + 2][1], m1.w, acc);
                acc = fmaf(w[p + 2][2], m8,   acc);
                // strict > keeps FIRST max (jnp.argmax tie-break)
                if (acc > best[p]) { best[p] = acc; bi[p] = f; }
            }
        }

        // ---- one-hot + horizontal 5-tap via shfl (lane = column) ----
#pragma unroll
        for (int p = 0; p < 4; p++) {
            const int idx = (best[p] < THRESH) ? NOR : bi[p];
            const u64 oh = (idx < NOR) ? (1ULL << (idx << 3)) : 0ULL;
            const u64 t1 = __shfl_down_sync(0xFFFFFFFFu, oh, 1);
            const u64 t2 = __shfl_down_sync(0xFFFFFFFFu, oh, 2);
            const u64 t3 = __shfl_down_sync(0xFFFFFFFFu, oh, 3);
            const u64 t4 = __shfl_down_sync(0xFFFFFFFFu, oh, 4);
            h[4 + p] = oh + t1 + t2 + t3 + t4;   // valid for lanes 0..27
        }

        // ---- emit 4 output rows o = ib-4 .. ib-1 (skip warm-up block) ----
        if (k >= 1) {
#pragma unroll
            for (int p = 0; p < 4; p++) {
                const int o = ib - 4 + p;
                if (colv && o < OUT_H) {
                    const u64 v = h[p] + h[p + 1] + h[p + 2] + h[p + 3] + h[p + 4];
                    const unsigned lo = (unsigned)v, hi = (unsigned)(v >> 32);
                    float* q = ob + (size_t)o * OUT_W + gx0;
#pragma unroll
                    for (int bin = 0; bin < 8; bin++) {
                        q[(size_t)bin * plane] =
                            cnt_scale((bin < 4) ? lo : hi, bin & 3);
                    }
                    const unsigned s8 =
                        __dp4a(lo, 0x01010101u, __dp4a(hi, 0x01010101u, 0u));
                    q[(size_t)8 * plane] = cnt_scale(25u - s8, 0);
                }
            }
        }

        // ---- shift rings ----
#pragma unroll
        for (int j = 0; j < 4; j++) h[j] = h[4 + j];
#pragma unroll
        for (int t = 0; t < 3; t++) { w[0][t] = w[4][t]; w[1][t] = w[5][t]; }
    }
}

extern "C" void kernel_launch(void* const* d_in, const int* in_sizes, int n_in,
                              void* d_out, int out_size)
{
    const float* x     = (const float*)d_in[0];   // [B,1,1024,1024]
    const float* masks = (const float*)d_in[1];   // [8,1,3,3]
    float* out = (float*)d_out;                   // [B,9,1018,1018]

    const int batch = in_sizes[0] / (1024 * 1024);

    dim3 grid((OUT_W + SW - 1) / SW, batch);      // 37 x 16 = 592 CTAs
    ehd_march_kernel<<<grid, 256>>>(x, masks, out);
}

// round 9
// speedup vs baseline: 1.0072x; 1.0072x over previous
#include <cuda_runtime.h>

// EHD layer, fully fused, v8 (= v5 + packed f32x2 conv):
//   3x3 conv (8 filters) -> argmax+thresh -> byte-packed one-hot ->
//   separable 5x5 box sum -> magic-number unpack -> out[B,9,1018,1018].
//
// v8 vs v5:
//  - conv uses fma.rn.f32x2 (SASS FFMA2, unreachable from C++): index rows
//    paired (p,p+2)/(p+1,p+3) so both pairs share window packs
//    pj[j]=(w[j],w[j+2]). 288 scalar FFMA -> 72 dual FMA2 + 12 packs.
//  - masks stored DUPLICATED in smem ((m,m) adjacent) so packed taps load
//    as 4xLDS.128 + 1xLDS.64 per filter.
//  - per-lane fma.rn rounding == fmaf -> bit-identical argmax.

#define NOR    8
#define NBINS  9
#define OUT_H  1018
#define OUT_W  1018
#define THRESH 0.9f

#define T   28            // output tile
#define IT  32            // index tile  (T+4)
#define LT  34            // input tile  (T+6)

#define NTHREADS 256

typedef unsigned long long u64;

__device__ __forceinline__ u64 pack2(float lo, float hi) {
    u64 r; asm("mov.b64 %0, {%1, %2};" : "=l"(r) : "f"(lo), "f"(hi)); return r;
}
__device__ __forceinline__ void unpack2(u64 v, float& lo, float& hi) {
    asm("mov.b64 {%0, %1}, %2;" : "=f"(lo), "=f"(hi) : "l"(v));
}
__device__ __forceinline__ u64 mul2(u64 a, u64 b) {
    u64 d; asm("mul.rn.f32x2 %0, %1, %2;" : "=l"(d) : "l"(a), "l"(b)); return d;
}
__device__ __forceinline__ u64 fma2(u64 a, u64 b, u64 c) {
    u64 d; asm("fma.rn.f32x2 %0, %1, %2, %3;" : "=l"(d) : "l"(a), "l"(b), "l"(c)); return d;
}

__device__ __forceinline__ float cnt_scale(unsigned word, int byte_sel) {
    // word's byte[byte_sel] = count in 0..25 -> count * fl(1/25), exact
    const unsigned bits = __byte_perm(word, 0x4B000000u, 0x7440 | byte_sel);
    return fmaf(__int_as_float(bits), (1.0f / 25.0f),
                -(8388608.0f * (1.0f / 25.0f)));
}

__global__ __launch_bounds__(NTHREADS, 5)
void ehd_fused_kernel(const float* __restrict__ x,
                      const float* __restrict__ masks,
                      float* __restrict__ out)
{
    __shared__ float s_in[LT][36];        // 34x36 f32
    __shared__ __align__(16) float s_m2[NOR * 20];  // duplicated taps, 80B/filter
    __shared__ u64 s_oh[IT][36];          // byte-packed one-hot (cols 32..35 = 0)
    __shared__ u64 s_h [IT][36];          // horizontal 5-sums (16B-aligned even cols)

    const int tid  = threadIdx.x;
    const int lane = tid & 31;
    const int wid  = tid >> 5;
    const int ox   = blockIdx.x * T;
    const int oy   = blockIdx.y * T;
    const int b    = blockIdx.z;

    if (tid < NOR * 9) {
        const int f = tid / 9, j = tid - f * 9;
        const float m = masks[tid];
        s_m2[f * 20 + 2 * j]     = m;   // duplicated: (m, m)
        s_m2[f * 20 + 2 * j + 1] = m;
    }
    if (tid < IT * 4) s_oh[tid >> 2][32 + (tid & 3)] = 0ULL;  // zero halo pad

    // ---- stage 1: load 34x34 input tile (zero-pad OOB) ----
    const float* xb = x + (size_t)b * (1024 * 1024);
    for (int r = wid; r < LT; r += 8) {
        const int gy = oy + r;
        for (int c = lane; c < LT; c += 32) {
            const int gx = ox + c;
            float v = 0.0f;
            if (gy < 1024 && gx < 1024) v = xb[gy * 1024 + gx];
            s_in[r][c] = v;
        }
    }
    __syncthreads();

    // ---- stage 2: dual-lane conv + argmax + threshold + one-hot ----
    // thread -> column c = lane, rows rbase..rbase+3.
    // Accumulator pairs: A=(p0,p2) uses pj[0..2], B=(p1,p3) uses pj[1..3],
    // where pj[j] = (w[j], w[j+2]).
    {
        const int c     = lane;
        const int rbase = wid << 2;

        u64 pj[4][3];
#pragma unroll
        for (int j = 0; j < 4; j++)
#pragma unroll
            for (int k = 0; k < 3; k++)
                pj[j][k] = pack2(s_in[rbase + j][c + k],
                                 s_in[rbase + j + 2][c + k]);

        float best[4];
        int   bi[4];
#pragma unroll
        for (int p = 0; p < 4; p++) { best[p] = -3.4e38f; bi[p] = 0; }

#pragma unroll
        for (int f = 0; f < NOR; f++) {
            const ulonglong2* mp = (const ulonglong2*)&s_m2[f * 20];
            const ulonglong2 q0 = mp[0];   // (m0,m0),(m1,m1)
            const ulonglong2 q1 = mp[1];   // (m2,m2),(m3,m3)
            const ulonglong2 q2 = mp[2];   // (m4,m4),(m5,m5)
            const ulonglong2 q3 = mp[3];   // (m6,m6),(m7,m7)
            const u64 m8 = *(const u64*)&s_m2[f * 20 + 16];

#pragma unroll
            for (int pp = 0; pp < 2; pp++) {          // pp=0 -> (p0,p2); pp=1 -> (p1,p3)
                u64 acc = mul2(pj[pp][0], q0.x);
                acc = fma2(pj[pp    ][1], q0.y, acc);
                acc = fma2(pj[pp    ][2], q1.x, acc);
                acc = fma2(pj[pp + 1][0], q1.y, acc);
                acc = fma2(pj[pp + 1][1], q2.x, acc);
                acc = fma2(pj[pp + 1][2], q2.y, acc);
                acc = fma2(pj[pp + 2][0], q3.x, acc);
                acc = fma2(pj[pp + 2][1], q3.y, acc);
                acc = fma2(pj[pp + 2][2], m8,   acc);
                float alo, ahi;                        // alo -> px pp, ahi -> px pp+2
                unpack2(acc, alo, ahi);
                // strict > keeps FIRST max (jnp.argmax tie-break)
                if (alo > best[pp    ]) { best[pp    ] = alo; bi[pp    ] = f; }
                if (ahi > best[pp + 2]) { best[pp + 2] = ahi; bi[pp + 2] = f; }
            }
        }
#pragma unroll
        for (int p = 0; p < 4; p++) {
            const int idx = (best[p] < THRESH) ? NOR : bi[p];
            // bins 0..7 -> one byte of a u64; bin 8 (no-edge) -> 0 (implicit)
            s_oh[rbase + p][c] = (idx < NOR) ? (1ULL << (idx << 3)) : 0ULL;
        }
    }
    __syncthreads();

    // ---- stage 3: horizontal 5-tap sliding sum, 128-bit smem traffic ----
    {
        const int r  = tid >> 3;
        const int c0 = (tid & 7) << 2;
        const ulonglong2* src = (const ulonglong2*)&s_oh[r][c0];
        const ulonglong2 p0 = src[0], p1 = src[1], p2 = src[2], p3 = src[3];
        const u64 a = p0.x, bb = p0.y, cc = p1.x, d = p1.y,
                  e = p2.x, f  = p2.y, g  = p3.x, h = p3.y;
        const u64 s0 = a + bb + cc + d + e;
        const u64 s1 = s0 - a  + f;
        const u64 s2 = s1 - bb + g;
        const u64 s3 = s2 - cc + h;
        ulonglong2* dst = (ulonglong2*)&s_h[r][c0];
        dst[0] = make_ulonglong2(s0, s1);
        dst[1] = make_ulonglong2(s2, s3);
    }
    __syncthreads();

    // ---- stage 4: vertical 5-tap on column pairs, unpack, float2 stores ----
    const size_t plane = (size_t)OUT_H * OUT_W;
    float* ob = out + (size_t)b * NBINS * plane;
#pragma unroll
    for (int it = 0; it < 2; it++) {
        const int u = tid + it * NTHREADS;
        if (u < 14 * T) {
            const int r  = u / 14;
            const int c  = (u - r * 14) * 2;
            const int gy = oy + r, gx = ox + c;
            if (gy < OUT_H && gx + 1 < OUT_W) {
                ulonglong2 q0 = *(const ulonglong2*)&s_h[r    ][c];
                ulonglong2 q1 = *(const ulonglong2*)&s_h[r + 1][c];
                ulonglong2 q2 = *(const ulonglong2*)&s_h[r + 2][c];
                ulonglong2 q3 = *(const ulonglong2*)&s_h[r + 3][c];
                ulonglong2 q4 = *(const ulonglong2*)&s_h[r + 4][c];
                const u64 v0 = q0.x + q1.x + q2.x + q3.x + q4.x;
                const u64 v1 = q0.y + q1.y + q2.y + q3.y + q4.y;
                const unsigned lo0 = (unsigned)v0, hi0 = (unsigned)(v0 >> 32);
                const unsigned lo1 = (unsigned)v1, hi1 = (unsigned)(v1 >> 32);

                float* p = ob + (size_t)gy * OUT_W + gx;
#pragma unroll
                for (int bin = 0; bin < 8; bin++) {
                    float2 v;
                    v.x = cnt_scale((bin < 4) ? lo0 : hi0, bin & 3);
                    v.y = cnt_scale((bin < 4) ? lo1 : hi1, bin & 3);
                    *(float2*)(p + (size_t)bin * plane) = v;
                }
                const unsigned s0 = __dp4a(lo0, 0x01010101u, __dp4a(hi0, 0x01010101u, 0u));
                const unsigned s1 = __dp4a(lo1, 0x01010101u, __dp4a(hi1, 0x01010101u, 0u));
                float2 v8;
                v8.x = cnt_scale(25u - s0, 0);
                v8.y = cnt_scale(25u - s1, 0);
                *(float2*)(p + (size_t)8 * plane) = v8;
            }
        }
    }
}

extern "C" void kernel_launch(void* const* d_in, const int* in_sizes, int n_in,
                              void* d_out, int out_size)
{
    const float* x     = (const float*)d_in[0];   // [B,1,1024,1024]
    const float* masks = (const float*)d_in[1];   // [8,1,3,3]
    float* out = (float*)d_out;                   // [B,9,1018,1018]

    const int batch = in_sizes[0] / (1024 * 1024);

    dim3 grid((OUT_W + T - 1) / T, (OUT_H + T - 1) / T, batch);
    ehd_fused_kernel<<<grid, NTHREADS>>>(x, masks, out);
}

// round 10
// speedup vs baseline: 1.2859x; 1.2767x over previous
#include <cuda_runtime.h>

// EHD layer v9: two-stage fused kernel, minimal smem.
//   3x3 conv (8 filters) -> argmax+thresh -> byte-packed one-hot ->
//   separable 5x5 box sum -> magic-number unpack -> out[B,9,1018,1018].
//
// v9 vs v5:
//  - stage 2 is ROW-mapped (thread = 4 horizontal px): window = 3 rows x 6
//    cols loaded DIRECTLY from global as LDG.128+LDG.64 per row (L1 serves
//    the 3x vertical redundancy). s_in + stage 1 + one barrier deleted.
//  - horizontal 5-tap via one predicated shfl_down(1): neighbor quad comes
//    from lane+1 (or zeros at the 32-col group end). s_oh + barrier deleted.
//  - single __syncthreads; smem = s_h only (9KB).

#define NOR    8
#define NBINS  9
#define OUT_H  1018
#define OUT_W  1018
#define THRESH 0.9f

#define T   28            // output tile
#define IT  32            // index tile (T+4)

#define NTHREADS 256

typedef unsigned long long u64;

__constant__ float c_masks[NOR * 9];

__device__ __forceinline__ float cnt_scale(unsigned word, int byte_sel) {
    // word's byte[byte_sel] = count in 0..25 -> count * fl(1/25), exact
    const unsigned bits = __byte_perm(word, 0x4B000000u, 0x7440 | byte_sel);
    return fmaf(__int_as_float(bits), (1.0f / 25.0f),
                -(8388608.0f * (1.0f / 25.0f)));
}

__global__ __launch_bounds__(NTHREADS, 5)
void ehd_fused_kernel(const float* __restrict__ x,
                      float* __restrict__ out)
{
    __shared__ u64 s_h[IT][36];   // horizontal 5-sums (16B-aligned even cols)

    const int tid  = threadIdx.x;
    const int lane = tid & 31;
    const int ox   = blockIdx.x * T;
    const int oy   = blockIdx.y * T;
    const int b    = blockIdx.z;

    const int r  = tid >> 3;          // index row within tile (0..31)
    const int c0 = (tid & 7) << 2;    // index col group (0,4,...,28)
    const int gx = ox + c0;           // global col of first px (mult of 4)
    const int gy = oy + r;            // global row of index px

    const float* xb = x + (size_t)b * (1024 * 1024);

    // ---- stage A: load 3x6 input window straight from global ----
    float w[3][6];
    if (ox + 34 <= 1024 && oy + 34 <= 1024) {
        // fast path: whole 34x34 input footprint in-bounds (36/37 tiles each way)
#pragma unroll
        for (int j = 0; j < 3; j++) {
            const float* row = xb + (gy + j) * 1024 + gx;
            const float4 a = *(const float4*)row;       // gx multiple of 4
            const float2 bb = *(const float2*)(row + 4);
            w[j][0] = a.x; w[j][1] = a.y; w[j][2] = a.z;
            w[j][3] = a.w; w[j][4] = bb.x; w[j][5] = bb.y;
        }
    } else {
        // slow path (edge tiles): per-element predicated, zero-fill OOB.
        // OOB zeros only feed index px whose outputs are clipped below.
#pragma unroll
        for (int j = 0; j < 3; j++) {
            const int yy = gy + j;
            const bool yv = (yy < 1024);
            const float* row = xb + yy * 1024 + gx;
#pragma unroll
            for (int k = 0; k < 6; k++)
                w[j][k] = (yv && (gx + k < 1024)) ? row[k] : 0.0f;
        }
    }

    // ---- stage B: conv (8 filters) + argmax + threshold, 4 horizontal px ----
    float best[4];
    int   bi[4];
#pragma unroll
    for (int q = 0; q < 4; q++) { best[q] = -3.4e38f; bi[q] = 0; }

#pragma unroll
    for (int f = 0; f < NOR; f++) {
        const float m0 = c_masks[f * 9 + 0], m1 = c_masks[f * 9 + 1], m2 = c_masks[f * 9 + 2];
        const float m3 = c_masks[f * 9 + 3], m4 = c_masks[f * 9 + 4], m5 = c_masks[f * 9 + 5];
        const float m6 = c_masks[f * 9 + 6], m7 = c_masks[f * 9 + 7], m8 = c_masks[f * 9 + 8];
#pragma unroll
        for (int q = 0; q < 4; q++) {
            float acc = w[0][q] * m0;
            acc = fmaf(w[0][q + 1], m1, acc);
            acc = fmaf(w[0][q + 2], m2, acc);
            acc = fmaf(w[1][q    ], m3, acc);
            acc = fmaf(w[1][q + 1], m4, acc);
            acc = fmaf(w[1][q + 2], m5, acc);
            acc = fmaf(w[2][q    ], m6, acc);
            acc = fmaf(w[2][q + 1], m7, acc);
            acc = fmaf(w[2][q + 2], m8, acc);
            // strict > keeps FIRST max (jnp.argmax tie-break)
            if (acc > best[q]) { best[q] = acc; bi[q] = f; }
        }
    }

    // byte-packed one-hot: bins 0..7 -> one byte of a u64; bin 8 implicit
    u64 oh[4];
#pragma unroll
    for (int q = 0; q < 4; q++) {
        const int idx = (best[q] < THRESH) ? NOR : bi[q];
        oh[q] = (idx < NOR) ? (1ULL << (idx << 3)) : 0ULL;
    }

    // ---- stage C: horizontal 5-tap via shfl (neighbor quad = lane+1) ----
    // cols c0+4..c0+7 live in lane+1's oh[0..3]; for the last group (c0=28)
    // they are the zero pad beyond the index tile.
    const bool has_nbr = ((lane & 7) != 7);
    u64 n[4];
#pragma unroll
    for (int q = 0; q < 4; q++) {
        const u64 t = __shfl_down_sync(0xFFFFFFFFu, oh[q], 1);
        n[q] = has_nbr ? t : 0ULL;
    }
    const u64 h0 = oh[0] + oh[1] + oh[2] + oh[3] + n[0];
    const u64 h1 = h0 - oh[0] + n[1];
    const u64 h2 = h1 - oh[1] + n[2];
    const u64 h3 = h2 - oh[2] + n[3];
    {
        ulonglong2* dst = (ulonglong2*)&s_h[r][c0];
        dst[0] = make_ulonglong2(h0, h1);
        dst[1] = make_ulonglong2(h2, h3);
    }
    __syncthreads();   // the only barrier

    // ---- stage D: vertical 5-tap on column pairs, unpack, float2 stores ----
    const size_t plane = (size_t)OUT_H * OUT_W;
    float* ob = out + (size_t)b * NBINS * plane;
#pragma unroll
    for (int it = 0; it < 2; it++) {
        const int u = tid + it * NTHREADS;
        if (u < 14 * T) {
            const int rr = u / 14;
            const int cc = (u - rr * 14) * 2;
            const int oyy = oy + rr, oxx = ox + cc;
            if (oyy < OUT_H && oxx + 1 < OUT_W) {
                ulonglong2 q0 = *(const ulonglong2*)&s_h[rr    ][cc];
                ulonglong2 q1 = *(const ulonglong2*)&s_h[rr + 1][cc];
                ulonglong2 q2 = *(const ulonglong2*)&s_h[rr + 2][cc];
                ulonglong2 q3 = *(const ulonglong2*)&s_h[rr + 3][cc];
                ulonglong2 q4 = *(const ulonglong2*)&s_h[rr + 4][cc];
                const u64 v0 = q0.x + q1.x + q2.x + q3.x + q4.x;
                const u64 v1 = q0.y + q1.y + q2.y + q3.y + q4.y;
                const unsigned lo0 = (unsigned)v0, hi0 = (unsigned)(v0 >> 32);
                const unsigned lo1 = (unsigned)v1, hi1 = (unsigned)(v1 >> 32);

                float* p = ob + (size_t)oyy * OUT_W + oxx;
#pragma unroll
                for (int bin = 0; bin < 8; bin++) {
                    float2 v;
                    v.x = cnt_scale((bin < 4) ? lo0 : hi0, bin & 3);
                    v.y = cnt_scale((bin < 4) ? lo1 : hi1, bin & 3);
                    *(float2*)(p + (size_t)bin * plane) = v;
                }
                // bin 8 = 25 - sum of the other 8 counts
                const unsigned s0 = __dp4a(lo0, 0x01010101u, __dp4a(hi0, 0x01010101u, 0u));
                const unsigned s1 = __dp4a(lo1, 0x01010101u, __dp4a(hi1, 0x01010101u, 0u));
                float2 v8;
                v8.x = cnt_scale(25u - s0, 0);
                v8.y = cnt_scale(25u - s1, 0);
                *(float2*)(p + (size_t)8 * plane) = v8;
            }
        }
    }
}

extern "C" void kernel_launch(void* const* d_in, const int* in_sizes, int n_in,
                              void* d_out, int out_size)
{
    const float* x     = (const float*)d_in[0];   // [B,1,1024,1024]
    const float* masks = (const float*)d_in[1];   // [8,1,3,3]
    float* out = (float*)d_out;                   // [B,9,1018,1018]

    const int batch = in_sizes[0] / (1024 * 1024);

    // masks -> constant bank (device-to-device async copy: graph-capturable)
    cudaMemcpyToSymbolAsync(c_masks, masks, NOR * 9 * sizeof(float), 0,
                            cudaMemcpyDeviceToDevice);

    dim3 grid((OUT_W + T - 1) / T, (OUT_H + T - 1) / T, batch);
    ehd_fused_kernel<<<grid, NTHREADS>>>(x, out);
}